// round 3
// baseline (speedup 1.0000x reference)
#include <cuda_runtime.h>
#include <math.h>

#define B_       16
#define HDIM     256
#define WDIM     256
#define C_       64
#define HW       (HDIM * WDIM)           // 65536
#define CONV_NUM 7
#define P_       128                      // partial blocks per batch

// Scratch (allocation-free rule: __device__ globals)
__device__ float4 g_pmax[B_ * P_ * (C_ / 4)];   // 512 KB
__device__ float4 g_psum[B_ * P_ * (C_ / 4)];   // 512 KB
__device__ float  g_scores[B_ * C_];            // 4 KB

// ---------------------------------------------------------------------------
// Kernel A: partial max + sum over pixels. grid (P_, B_), block 256.
// Each block reduces HW/P_ = 512 pixels; accesses are perfectly linear float4.
// ---------------------------------------------------------------------------
__global__ __launch_bounds__(256) void reduce_kernel(const float4* __restrict__ feats4)
{
    const int tid  = threadIdx.x;
    const int p    = blockIdx.x;
    const int b    = blockIdx.y;

    const int PIX_PER_BLK = HW / P_;          // 512
    const int ITERS       = PIX_PER_BLK / 16; // 32

    const float4* src = feats4 + ((size_t)b * HW + (size_t)p * PIX_PER_BLK) * (C_ / 4);

    float4 vmax = make_float4(-INFINITY, -INFINITY, -INFINITY, -INFINITY);
    float4 vsum = make_float4(0.f, 0.f, 0.f, 0.f);

    #pragma unroll 8
    for (int i = 0; i < ITERS; i++) {
        float4 v = src[i * 256 + tid];   // linear: i*256 + tid
        vmax.x = fmaxf(vmax.x, v.x); vsum.x += v.x;
        vmax.y = fmaxf(vmax.y, v.y); vsum.y += v.y;
        vmax.z = fmaxf(vmax.z, v.z); vsum.z += v.z;
        vmax.w = fmaxf(vmax.w, v.w); vsum.w += v.w;
    }

    __shared__ float4 smax[256];
    __shared__ float4 ssum[256];
    smax[tid] = vmax;
    ssum[tid] = vsum;
    __syncthreads();

    // Threads 0..15 own channel-group tid; combine the 16 pixel-sub lanes.
    if (tid < 16) {
        float4 m = smax[tid];
        float4 s = ssum[tid];
        #pragma unroll
        for (int j = 1; j < 16; j++) {
            float4 m2 = smax[tid + 16 * j];
            float4 s2 = ssum[tid + 16 * j];
            m.x = fmaxf(m.x, m2.x); s.x += s2.x;
            m.y = fmaxf(m.y, m2.y); s.y += s2.y;
            m.z = fmaxf(m.z, m2.z); s.z += s2.z;
            m.w = fmaxf(m.w, m2.w); s.w += s2.w;
        }
        g_pmax[(b * P_ + p) * 16 + tid] = m;
        g_psum[(b * P_ + p) * 16 + tid] = s;
    }
}

// ---------------------------------------------------------------------------
// Kernel B: finish reduction + 7-layer residual PReLU MLP (both branches) +
// sigmoid. grid B_, block C_ (64). Tiny — latency only.
// ---------------------------------------------------------------------------
__global__ __launch_bounds__(64) void mlp_kernel(const float* __restrict__ W1,
                                                 const float* __restrict__ b1,
                                                 const float* __restrict__ a1)
{
    const int b = blockIdx.x;
    const int c = threadIdx.x;

    const float* pmax = (const float*)g_pmax;
    const float* psum = (const float*)g_psum;

    float m = -INFINITY;
    float s = 0.f;
    #pragma unroll 4
    for (int p = 0; p < P_; p++) {
        m = fmaxf(m, pmax[(b * P_ + p) * C_ + c]);
        s += psum[(b * P_ + p) * C_ + c];
    }

    float xm = m;
    float xa = s * (1.f / (float)HW);

    __shared__ float smx[C_];
    __shared__ float sma[C_];

    for (int k = 0; k < CONV_NUM; k++) {
        const float* Wk = W1 + (size_t)k * C_ * C_ + (size_t)c * C_; // row c of W1[k]
        float bias  = b1[k * C_ + c];
        float alpha = a1[k];

        __syncthreads();
        smx[c] = xm;
        sma[c] = xa;
        __syncthreads();

        float ym = bias, ya = bias;
        #pragma unroll
        for (int d = 0; d < C_; d++) {
            float w = Wk[d];
            ym += smx[d] * w;
            ya += sma[d] * w;
        }
        ym = (ym >= 0.f ? ym : alpha * ym) + xm;
        ya = (ya >= 0.f ? ya : alpha * ya) + xa;
        xm = ym;
        xa = ya;
    }

    float z = xm + xa;
    g_scores[b * C_ + c] = 1.f / (1.f + expf(-z));
}

// ---------------------------------------------------------------------------
// Kernel C: out = features * scores[b][c]. 4 float4s per thread, strided so
// consecutive threads stay coalesced. grid (1024, 16), block 256.
// ---------------------------------------------------------------------------
#define SCALE_V 4
__global__ __launch_bounds__(256) void scale_kernel(const float4* __restrict__ feats4,
                                                    float4* __restrict__ out4)
{
    const int b = blockIdx.y;
    const size_t base = (size_t)b * (HW * (C_ / 4));
    // Each block covers SCALE_V consecutive 256-float4 chunks.
    const int idx0 = (blockIdx.x * SCALE_V) * 256 + threadIdx.x;

    const float4* sc4 = (const float4*)g_scores;
    // channel group repeats every 16 float4s; idx0 and idx0+256k share (idx&15)
    float4 s = __ldg(&sc4[b * 16 + (idx0 & 15)]);

    float4 v[SCALE_V];
    #pragma unroll
    for (int i = 0; i < SCALE_V; i++)
        v[i] = feats4[base + idx0 + i * 256];
    #pragma unroll
    for (int i = 0; i < SCALE_V; i++) {
        v[i].x *= s.x; v[i].y *= s.y; v[i].z *= s.z; v[i].w *= s.w;
        out4[base + idx0 + i * 256] = v[i];
    }
}

// ---------------------------------------------------------------------------
extern "C" void kernel_launch(void* const* d_in, const int* in_sizes, int n_in,
                              void* d_out, int out_size)
{
    const float4* feats4 = (const float4*)d_in[0];
    const float*  W1     = (const float*)d_in[1];
    const float*  b1     = (const float*)d_in[2];
    const float*  a1     = (const float*)d_in[3];
    float4* out4 = (float4*)d_out;

    dim3 gridA(P_, B_);
    reduce_kernel<<<gridA, 256>>>(feats4);

    mlp_kernel<<<B_, C_>>>(W1, b1, a1);

    dim3 gridC((HW * (C_ / 4)) / (256 * SCALE_V), B_);   // (1024, 16)
    scale_kernel<<<gridC, 256>>>(feats4, out4);

    (void)in_sizes; (void)n_in; (void)out_size;
}

// round 4
// speedup vs baseline: 1.0371x; 1.0371x over previous
#include <cuda_runtime.h>
#include <math.h>

#define B_       16
#define HDIM     256
#define WDIM     256
#define C_       64
#define HW       (HDIM * WDIM)           // 65536
#define CONV_NUM 7
#define P_       128                      // partial blocks per batch

// Scratch (allocation-free rule: __device__ globals)
__device__ float4 g_pmax[B_ * P_ * (C_ / 4)];   // 512 KB
__device__ float4 g_psum[B_ * P_ * (C_ / 4)];   // 512 KB
__device__ float  g_scores[B_ * C_];            // 4 KB

// ---------------------------------------------------------------------------
// Kernel A: partial max + sum over pixels. grid (P_, B_), block 256.
// Each block reduces HW/P_ = 512 pixels; accesses are perfectly linear float4.
// Streaming loads (__ldcs): data is not reused before eviction.
// ---------------------------------------------------------------------------
__global__ __launch_bounds__(256) void reduce_kernel(const float4* __restrict__ feats4)
{
    const int tid  = threadIdx.x;
    const int p    = blockIdx.x;
    const int b    = blockIdx.y;

    const int PIX_PER_BLK = HW / P_;          // 512
    const int ITERS       = PIX_PER_BLK / 16; // 32

    const float4* src = feats4 + ((size_t)b * HW + (size_t)p * PIX_PER_BLK) * (C_ / 4);

    float4 vmax = make_float4(-INFINITY, -INFINITY, -INFINITY, -INFINITY);
    float4 vsum = make_float4(0.f, 0.f, 0.f, 0.f);

    #pragma unroll 8
    for (int i = 0; i < ITERS; i++) {
        float4 v = __ldcs(&src[i * 256 + tid]);   // linear: i*256 + tid
        vmax.x = fmaxf(vmax.x, v.x); vsum.x += v.x;
        vmax.y = fmaxf(vmax.y, v.y); vsum.y += v.y;
        vmax.z = fmaxf(vmax.z, v.z); vsum.z += v.z;
        vmax.w = fmaxf(vmax.w, v.w); vsum.w += v.w;
    }

    __shared__ float4 smax[256];
    __shared__ float4 ssum[256];
    smax[tid] = vmax;
    ssum[tid] = vsum;
    __syncthreads();

    // Threads 0..15 own channel-group tid; combine the 16 pixel-sub lanes.
    if (tid < 16) {
        float4 m = smax[tid];
        float4 s = ssum[tid];
        #pragma unroll
        for (int j = 1; j < 16; j++) {
            float4 m2 = smax[tid + 16 * j];
            float4 s2 = ssum[tid + 16 * j];
            m.x = fmaxf(m.x, m2.x); s.x += s2.x;
            m.y = fmaxf(m.y, m2.y); s.y += s2.y;
            m.z = fmaxf(m.z, m2.z); s.z += s2.z;
            m.w = fmaxf(m.w, m2.w); s.w += s2.w;
        }
        g_pmax[(b * P_ + p) * 16 + tid] = m;
        g_psum[(b * P_ + p) * 16 + tid] = s;
    }
}

// ---------------------------------------------------------------------------
// Kernel B: finish reduction + 7-layer residual PReLU MLP (both branches) +
// sigmoid. grid B_, block C_ (64). Tiny — latency only.
// ---------------------------------------------------------------------------
__global__ __launch_bounds__(64) void mlp_kernel(const float* __restrict__ W1,
                                                 const float* __restrict__ b1,
                                                 const float* __restrict__ a1)
{
    const int b = blockIdx.x;
    const int c = threadIdx.x;

    const float* pmax = (const float*)g_pmax;
    const float* psum = (const float*)g_psum;

    float m = -INFINITY;
    float s = 0.f;
    #pragma unroll 4
    for (int p = 0; p < P_; p++) {
        m = fmaxf(m, pmax[(b * P_ + p) * C_ + c]);
        s += psum[(b * P_ + p) * C_ + c];
    }

    float xm = m;
    float xa = s * (1.f / (float)HW);

    __shared__ float smx[C_];
    __shared__ float sma[C_];

    for (int k = 0; k < CONV_NUM; k++) {
        const float* Wk = W1 + (size_t)k * C_ * C_ + (size_t)c * C_; // row c of W1[k]
        float bias  = b1[k * C_ + c];
        float alpha = a1[k];

        __syncthreads();
        smx[c] = xm;
        sma[c] = xa;
        __syncthreads();

        float ym = bias, ya = bias;
        #pragma unroll
        for (int d = 0; d < C_; d++) {
            float w = Wk[d];
            ym += smx[d] * w;
            ya += sma[d] * w;
        }
        ym = (ym >= 0.f ? ym : alpha * ym) + xm;
        ya = (ya >= 0.f ? ya : alpha * ya) + xa;
        xm = ym;
        xa = ya;
    }

    float z = xm + xa;
    g_scores[b * C_ + c] = 1.f / (1.f + expf(-z));
}

// ---------------------------------------------------------------------------
// Kernel C: out = features * scores[b][c]. 8 float4s per thread, stride-256
// within the block's region so every LDG/STG is fully coalesced. Streaming
// hints on both directions: no reuse, keep L2 out of the way.
// grid (512, 16), block 256.
// ---------------------------------------------------------------------------
#define SCALE_V 8
__global__ __launch_bounds__(256) void scale_kernel(const float4* __restrict__ feats4,
                                                    float4* __restrict__ out4)
{
    const int b = blockIdx.y;
    const size_t base = (size_t)b * (HW * (C_ / 4));
    // Each block covers SCALE_V consecutive 256-float4 chunks.
    const int idx0 = (blockIdx.x * SCALE_V) * 256 + threadIdx.x;

    const float4* sc4 = (const float4*)g_scores;
    // channel group repeats every 16 float4s; idx0 and idx0+256k share (idx&15)
    float4 s = __ldg(&sc4[b * 16 + (idx0 & 15)]);

    float4 v[SCALE_V];
    #pragma unroll
    for (int i = 0; i < SCALE_V; i++)
        v[i] = __ldcs(&feats4[base + idx0 + i * 256]);
    #pragma unroll
    for (int i = 0; i < SCALE_V; i++) {
        v[i].x *= s.x; v[i].y *= s.y; v[i].z *= s.z; v[i].w *= s.w;
        __stcs(&out4[base + idx0 + i * 256], v[i]);
    }
}

// ---------------------------------------------------------------------------
extern "C" void kernel_launch(void* const* d_in, const int* in_sizes, int n_in,
                              void* d_out, int out_size)
{
    const float4* feats4 = (const float4*)d_in[0];
    const float*  W1     = (const float*)d_in[1];
    const float*  b1     = (const float*)d_in[2];
    const float*  a1     = (const float*)d_in[3];
    float4* out4 = (float4*)d_out;

    dim3 gridA(P_, B_);
    reduce_kernel<<<gridA, 256>>>(feats4);

    mlp_kernel<<<B_, C_>>>(W1, b1, a1);

    dim3 gridC((HW * (C_ / 4)) / (256 * SCALE_V), B_);   // (512, 16)
    scale_kernel<<<gridC, 256>>>(feats4, out4);

    (void)in_sizes; (void)n_in; (void)out_size;
}